// round 10
// baseline (speedup 1.0000x reference)
#include <cuda_runtime.h>
#include <cuda_bf16.h>
#include <cstdint>

// Problem constants
#define T_SEQ  50
#define B_SZ   64
#define HIDN   512
#define NCODES 8192
#define KCODES 32
#define DEMO   32
#define ROWS   (T_SEQ * B_SZ)        // 3200
#define GCOLS  (4 * HIDN * 2)        // 4096

// ---------------- scratch (no allocations allowed) ----------------
__device__ float d_WcT [NCODES * HIDN];
__device__ float d_G   [ROWS * GCOLS];
__device__ float d_y   [ROWS * 2 * HIDN];
__device__ float d_hA  [2 * B_SZ * HIDN];                  // final h per dir
__device__ float d_feat[B_SZ * (2 * HIDN + DEMO)];
__device__ float d_hid [B_SZ * HIDN];
__device__ __nv_bfloat16 d_Asp[ROWS * 3 * 1024];           // split A, max K'=3072
__device__ __nv_bfloat16 d_Wsp[GCOLS * 3 * 1024];          // split W (input proj)
__device__ __nv_bfloat16 d_Whhsp[2 * 64 * 32 * 1536];      // split w_hh, block-contiguous
__device__ __nv_bfloat16 d_hspA[2 * B_SZ * 1536];          // h split ping
__device__ __nv_bfloat16 d_hspB[2 * B_SZ * 1536];          // h split pong
// grid-barrier state (monotonic generation; safe across graph replays)
__device__ unsigned g_cnt = 0;
__device__ unsigned g_gen = 0;

// =================== common PTX helpers ===================
__device__ __forceinline__ void mma16816(float* c, const uint32_t* a, const uint32_t* b) {
    asm volatile(
        "mma.sync.aligned.m16n8k16.row.col.f32.bf16.bf16.f32 "
        "{%0,%1,%2,%3}, {%4,%5,%6,%7}, {%8,%9}, {%0,%1,%2,%3};"
        : "+f"(c[0]), "+f"(c[1]), "+f"(c[2]), "+f"(c[3])
        : "r"(a[0]), "r"(a[1]), "r"(a[2]), "r"(a[3]), "r"(b[0]), "r"(b[1]));
}
#define LDSM_X4(r0, r1, r2, r3, addr) \
    asm volatile("ldmatrix.sync.aligned.m8n8.x4.shared.b16 {%0,%1,%2,%3}, [%4];" \
                 : "=r"(r0), "=r"(r1), "=r"(r2), "=r"(r3) : "r"(addr))
#define CP16(dst, src) \
    asm volatile("cp.async.cg.shared.global [%0], [%1], 16;" :: "r"(dst), "l"(src))
#define CP_COMMIT() asm volatile("cp.async.commit_group;" ::: "memory")
#define CP_WAIT(n)  asm volatile("cp.async.wait_group %0;" :: "n"(n) : "memory")

// ---------------- Wc transpose ----------------
__global__ void transpose_wc(const float* __restrict__ Wc, float* __restrict__ WcT) {
    __shared__ float tile[32][33];
    int c0 = blockIdx.x * 32, h0 = blockIdx.y * 32;
    int tx = threadIdx.x, ty = threadIdx.y;
#pragma unroll
    for (int i = 0; i < 32; i += 8)
        tile[ty + i][tx] = Wc[(h0 + ty + i) * NCODES + c0 + tx];
    __syncthreads();
#pragma unroll
    for (int i = 0; i < 32; i += 8)
        WcT[(c0 + ty + i) * HIDN + h0 + tx] = tile[tx][ty + i];
}

// ---------------- multi-hot embed with dedup, fused bf16 split output ----------------
// writes A' rows directly: [hi | lo | hi] at stride 1536 (layer0 K'=1536)
__global__ void embed_split(const int* __restrict__ codes,
                            const float* __restrict__ WcT,
                            const float* __restrict__ bc,
                            __nv_bfloat16* __restrict__ Ap) {
    int blk = blockIdx.x;
    int t = blk >> 6, b = blk & 63;
    __shared__ int sc[KCODES];
    __shared__ int nk;
    int tid = threadIdx.x;
    if (tid < KCODES) sc[tid] = codes[(b * T_SEQ + t) * KCODES + tid];
    __syncthreads();
    if (tid == 0) {
        int cnt = 0;
        for (int j = 0; j < KCODES; j++) {
            int cj = sc[j];
            bool dup = false;
            for (int i = 0; i < cnt; i++)
                if (sc[i] == cj) { dup = true; break; }
            if (!dup) sc[cnt++] = cj;
        }
        nk = cnt;
    }
    __syncthreads();
    int m = nk;
    for (int h = tid; h < HIDN; h += 256) {
        float acc = bc[h];
        for (int j = 0; j < m; j++)
            acc += WcT[sc[j] * HIDN + h];
        __nv_bfloat16 hi = __float2bfloat16(acc);
        __nv_bfloat16 lo = __float2bfloat16(acc - __bfloat162float(hi));
        size_t base = (size_t)blk * 1536;
        Ap[base + h] = hi; Ap[base + 512 + h] = lo; Ap[base + 1024 + h] = hi;
    }
}

// ---------------- bf16 split kernels ----------------
__global__ void split_A_k(const float* __restrict__ A, __nv_bfloat16* __restrict__ Ap,
                          int M, int K) {
    int idx = blockIdx.x * blockDim.x + threadIdx.x;
    if (idx >= M * K) return;
    int m = idx / K, k = idx - m * K;
    float a = A[idx];
    __nv_bfloat16 hi = __float2bfloat16(a);
    __nv_bfloat16 lo = __float2bfloat16(a - __bfloat162float(hi));
    size_t b = (size_t)m * 3 * K;
    Ap[b + k] = hi; Ap[b + K + k] = lo; Ap[b + 2 * K + k] = hi;
}
__global__ void split_W_k(const float* __restrict__ W, __nv_bfloat16* __restrict__ Wp,
                          int N, int K) {
    int idx = blockIdx.x * blockDim.x + threadIdx.x;
    if (idx >= N * K) return;
    int n = idx / K, k = idx - n * K;
    float w = W[idx];
    __nv_bfloat16 hi = __float2bfloat16(w);
    __nv_bfloat16 lo = __float2bfloat16(w - __bfloat162float(hi));
    size_t b = (size_t)n * 3 * K;
    Wp[b + k] = hi; Wp[b + K + k] = hi; Wp[b + 2 * K + k] = lo;
}
// split w_hh [2,2048,512] into block-contiguous layout:
// dst[((d*64+bx)*32 + c)*1536 + {k, 512+k, 1024+k}] = {hi, hi, lo}
// where row r = g*512+n, bx = n>>3, c = g*8 + (n&7)
__global__ void split_whh(const float* __restrict__ whh, __nv_bfloat16* __restrict__ Wp) {
    int idx = blockIdx.x * blockDim.x + threadIdx.x;
    if (idx >= 2 * 2048 * 512) return;
    int k = idx & 511;
    int r = (idx >> 9) & 2047;
    int d = idx >> 20;
    float w = whh[idx];
    __nv_bfloat16 hi = __float2bfloat16(w);
    __nv_bfloat16 lo = __float2bfloat16(w - __bfloat162float(hi));
    int n = r & 511, g = r >> 9;
    int bx = n >> 3, c = g * 8 + (n & 7);
    size_t base = ((size_t)(d * 64 + bx) * 32 + c) * 1536;
    Wp[base + k] = hi; Wp[base + 512 + k] = hi; Wp[base + 1024 + k] = lo;
}

// ---------------- mma.sync bf16 GEMM (input projections) ----------------
#define SSTRIDE 40
#define STAGES  3
#define STG_ELEM (128 * SSTRIDE)
__global__ void __launch_bounds__(256)
gemm_mma(const __nv_bfloat16* __restrict__ Ag,
         const __nv_bfloat16* __restrict__ Wg,
         const float* __restrict__ bias,
         float* __restrict__ C, int K3) {
    extern __shared__ __nv_bfloat16 gsm_[];
    __nv_bfloat16* sA = gsm_;
    __nv_bfloat16* sW = gsm_ + STAGES * STG_ELEM;
    const int tid = threadIdx.x, lane = tid & 31, wid = tid >> 5;
    const int wm = wid & 3, wn = wid >> 2;
    const int m0 = blockIdx.y * 128, n0 = blockIdx.x * 128;
    const int qr = lane >> 2, qc = (lane & 3) * 2;
    float acc[2][8][4] = {};

    const int lrow = tid >> 1;
    const int lseg = (tid & 1) * 16;
    const __nv_bfloat16* Asrc = Ag + (size_t)(m0 + lrow) * K3 + lseg;
    const __nv_bfloat16* Wsrc = Wg + (size_t)(n0 + lrow) * K3 + lseg;
    const uint32_t sA_u32 = (uint32_t)__cvta_generic_to_shared(sA);
    const uint32_t sW_u32 = (uint32_t)__cvta_generic_to_shared(sW);
    const uint32_t dstoff = (uint32_t)(lrow * SSTRIDE + lseg) * 2;

    const uint32_t aAddr0 = sA_u32 +
        (uint32_t)((wm * 32 + (lane & 15)) * SSTRIDE + ((lane >> 4) << 3)) * 2;
    const uint32_t bAddr0 = sW_u32 +
        (uint32_t)((wn * 64 + ((lane >> 4) << 3) + (lane & 7)) * SSTRIDE + (((lane >> 3) & 1) << 3)) * 2;

    const int nkb = K3 / 32;
#pragma unroll
    for (int s = 0; s < STAGES - 1; s++) {
        uint32_t d0 = (uint32_t)(s * STG_ELEM) * 2 + dstoff;
        const __nv_bfloat16* a = Asrc + s * 32;
        const __nv_bfloat16* w = Wsrc + s * 32;
        CP16(sA_u32 + d0, a); CP16(sA_u32 + d0 + 16, a + 8);
        CP16(sW_u32 + d0, w); CP16(sW_u32 + d0 + 16, w + 8);
        CP_COMMIT();
    }

    for (int kb = 0; kb < nkb; kb++) {
        const int lk = kb + STAGES - 1;
        if (lk < nkb) {
            uint32_t d0 = (uint32_t)((lk % STAGES) * STG_ELEM) * 2 + dstoff;
            const __nv_bfloat16* a = Asrc + lk * 32;
            const __nv_bfloat16* w = Wsrc + lk * 32;
            CP16(sA_u32 + d0, a); CP16(sA_u32 + d0 + 16, a + 8);
            CP16(sW_u32 + d0, w); CP16(sW_u32 + d0 + 16, w + 8);
        }
        CP_COMMIT();
        CP_WAIT(STAGES - 1);
        __syncthreads();

        const uint32_t soff = (uint32_t)((kb % STAGES) * STG_ELEM) * 2;
#pragma unroll
        for (int ks = 0; ks < 32; ks += 16) {
            uint32_t af[2][4];
#pragma unroll
            for (int mt = 0; mt < 2; mt++) {
                uint32_t addr = aAddr0 + soff + (uint32_t)(mt * 16 * SSTRIDE + ks) * 2;
                LDSM_X4(af[mt][0], af[mt][1], af[mt][2], af[mt][3], addr);
            }
            uint32_t bfr[4][4];
#pragma unroll
            for (int nt2 = 0; nt2 < 4; nt2++) {
                uint32_t addr = bAddr0 + soff + (uint32_t)(nt2 * 16 * SSTRIDE + ks) * 2;
                LDSM_X4(bfr[nt2][0], bfr[nt2][1], bfr[nt2][2], bfr[nt2][3], addr);
            }
#pragma unroll
            for (int mt = 0; mt < 2; mt++)
#pragma unroll
                for (int nt = 0; nt < 8; nt++)
                    mma16816(acc[mt][nt], af[mt], &bfr[nt >> 1][(nt & 1) * 2]);
        }
        __syncthreads();
    }

#pragma unroll
    for (int mt = 0; mt < 2; mt++) {
        int r = m0 + wm * 32 + mt * 16 + qr;
#pragma unroll
        for (int nt = 0; nt < 8; nt++) {
            int c = n0 + wn * 64 + nt * 8 + qc;
            float b0 = bias[c], b1 = bias[c + 1];
            float2 v0 = make_float2(acc[mt][nt][0] + b0, acc[mt][nt][1] + b1);
            float2 v1 = make_float2(acc[mt][nt][2] + b0, acc[mt][nt][3] + b1);
            *(float2*)(C + (size_t)r * GCOLS + c) = v0;
            *(float2*)(C + (size_t)(r + 8) * GCOLS + c) = v1;
        }
    }
}

// ---------------- fp32 SGEMM (classifier only) ----------------
template <bool RELU>
__global__ void sgemm_bias(const float* __restrict__ A, const float* __restrict__ W,
                           const float* __restrict__ bias, float* __restrict__ C,
                           int M, int N, int K) {
    __shared__ float As[2][8][132];
    __shared__ float Bs[2][8][132];
    const int t  = threadIdx.x;
    const int tx = t & 15, ty = t >> 4;
    const int m0 = blockIdx.y * 128, n0 = blockIdx.x * 128;
    const int lr = t >> 1;
    const int lk = (t & 1) * 4;
    float acc[8][8] = {};
    const bool aval = (m0 + lr) < M;
    const float* Arow = A + (size_t)(m0 + lr) * K + lk;
    const float* Wrow = W + (size_t)(n0 + lr) * K + lk;
    {
        float4 av = aval ? *(const float4*)(Arow) : make_float4(0.f, 0.f, 0.f, 0.f);
        float4 bv = *(const float4*)(Wrow);
        As[0][lk + 0][lr] = av.x; As[0][lk + 1][lr] = av.y; As[0][lk + 2][lr] = av.z; As[0][lk + 3][lr] = av.w;
        Bs[0][lk + 0][lr] = bv.x; Bs[0][lk + 1][lr] = bv.y; Bs[0][lk + 2][lr] = bv.z; Bs[0][lk + 3][lr] = bv.w;
    }
    __syncthreads();
    int buf = 0;
    for (int kb = 8; kb < K; kb += 8) {
        float4 av = aval ? *(const float4*)(Arow + kb) : make_float4(0.f, 0.f, 0.f, 0.f);
        float4 bv = *(const float4*)(Wrow + kb);
#pragma unroll
        for (int k = 0; k < 8; k++) {
            float a[8], b[8];
            *(float4*)&a[0] = *(const float4*)&As[buf][k][ty * 8];
            *(float4*)&a[4] = *(const float4*)&As[buf][k][ty * 8 + 4];
            *(float4*)&b[0] = *(const float4*)&Bs[buf][k][tx * 8];
            *(float4*)&b[4] = *(const float4*)&Bs[buf][k][tx * 8 + 4];
#pragma unroll
            for (int i = 0; i < 8; i++)
#pragma unroll
                for (int j = 0; j < 8; j++)
                    acc[i][j] += a[i] * b[j];
        }
        int nb = buf ^ 1;
        As[nb][lk + 0][lr] = av.x; As[nb][lk + 1][lr] = av.y; As[nb][lk + 2][lr] = av.z; As[nb][lk + 3][lr] = av.w;
        Bs[nb][lk + 0][lr] = bv.x; Bs[nb][lk + 1][lr] = bv.y; Bs[nb][lk + 2][lr] = bv.z; Bs[nb][lk + 3][lr] = bv.w;
        __syncthreads();
        buf = nb;
    }
#pragma unroll
    for (int k = 0; k < 8; k++) {
        float a[8], b[8];
        *(float4*)&a[0] = *(const float4*)&As[buf][k][ty * 8];
        *(float4*)&a[4] = *(const float4*)&As[buf][k][ty * 8 + 4];
        *(float4*)&b[0] = *(const float4*)&Bs[buf][k][tx * 8];
        *(float4*)&b[4] = *(const float4*)&Bs[buf][k][tx * 8 + 4];
#pragma unroll
        for (int i = 0; i < 8; i++)
#pragma unroll
            for (int j = 0; j < 8; j++)
                acc[i][j] += a[i] * b[j];
    }
#pragma unroll
    for (int i = 0; i < 8; i++) {
        int row = m0 + ty * 8 + i;
        if (row >= M) continue;
#pragma unroll
        for (int j = 0; j < 8; j++) {
            int col = n0 + tx * 8 + j;
            float v = acc[i][j] + bias[col];
            if (RELU) v = fmaxf(v, 0.f);
            C[(size_t)row * N + col] = v;
        }
    }
}

// ---------------- zero hsplit ping ----------------
__global__ void zero_hsp(__nv_bfloat16* __restrict__ h) {
    int i = blockIdx.x * blockDim.x + threadIdx.x;
    if (i < 2 * B_SZ * 1536) h[i] = __float2bfloat16(0.f);
}

// ---------------- persistent tensor-core LSTM scan ----------------
// grid (64, 2) = 128 blocks, 1/SM (158KB smem) -> co-resident, spin barrier safe.
// Block: dir d, hidden cols [bx*8, bx*8+8) x 4 gates = 32 output cols, M=64 batch.
// K'=1536 (split-2). W slice persistent in smem; h-split tile via 3-buf cp.async.
#define ACH    128                 // A chunk (k' elems)
#define ASTR   136                 // A smem row stride
#define WSTR   1544                // W smem row stride
#define NCHUNK (1536 / ACH)        // 12
__device__ __forceinline__ void grid_bar(unsigned nb) {
    __syncthreads();
    if (threadIdx.x == 0) {
        __threadfence();
        unsigned target = *(volatile unsigned*)&g_gen + 1;
        if (atomicAdd(&g_cnt, 1u) == nb - 1u) {
            g_cnt = 0;
            __threadfence();
            *(volatile unsigned*)&g_gen = target;
        } else {
            while (*(volatile unsigned*)&g_gen < target) { }
        }
        __threadfence();
    }
    __syncthreads();
}

__global__ void __launch_bounds__(256)
lstm_scan_mma(const float* __restrict__ G,            // [T*64, 4096]
              const __nv_bfloat16* __restrict__ Whhsp, // [2*64 blocks][32][1536]
              __nv_bfloat16* __restrict__ hspA,        // ping (zeroed for t=0)
              __nv_bfloat16* __restrict__ hspB,        // pong
              float* __restrict__ hfin,                // [2,64,512] final h
              float* __restrict__ y) {                 // [T*64, 1024] or nullptr
    extern __shared__ char smx[];
    __nv_bfloat16* Wsm = (__nv_bfloat16*)smx;                          // [32][WSTR]
    __nv_bfloat16* Asm = (__nv_bfloat16*)(smx + 32 * WSTR * 2);        // [3][64][ASTR]
    float* gsm = (float*)(smx + 32 * WSTR * 2 + 3 * 64 * ASTR * 2);    // [64][36]

    const int tid = threadIdx.x, lane = tid & 31, wid = tid >> 5;
    const int wm = wid & 3, wn = wid >> 2;
    const int d = blockIdx.y, bx = blockIdx.x, n0 = bx * 8;
    const int qr = lane >> 2, qc = (lane & 3) * 2;
    const int tn = tid & 7, tb = tid >> 3;

    // load W slice [32][1536] (contiguous in Whhsp) into smem
    {
        const __nv_bfloat16* Wg = Whhsp + (size_t)(d * 64 + bx) * 32 * 1536;
        for (int i = tid; i < 32 * 192; i += 256) {   // 192 = 1536/8 uint4 per row
            int r = i / 192, c8 = (i % 192) * 8;
            *(uint4*)(Wsm + r * WSTR + c8) = *(const uint4*)(Wg + r * 1536 + c8);
        }
    }
    __syncthreads();

    const uint32_t asm_base = (uint32_t)__cvta_generic_to_shared(Asm);
    const uint32_t wsm_base = (uint32_t)__cvta_generic_to_shared(Wsm);
    const int arow = tid >> 2, aseg = (tid & 3) * 32;     // cp.async: 4x16B per thread
    const uint32_t aAddr0 = asm_base +
        (uint32_t)((wm * 16 + (lane & 15)) * ASTR + ((lane >> 4) << 3)) * 2;
    const uint32_t bAddr0 = wsm_base +
        (uint32_t)((wn * 16 + ((lane >> 4) << 3) + (lane & 7)) * WSTR + (((lane >> 3) & 1) << 3)) * 2;

    float cv0 = 0.f, cv1 = 0.f;

    for (int t = 0; t < T_SEQ; t++) {
        const int t_eff = (d == 0) ? t : (T_SEQ - 1 - t);
        const __nv_bfloat16* hin = ((t & 1) ? hspB : hspA) + (size_t)d * 64 * 1536;
        __nv_bfloat16* hout = ((t & 1) ? hspA : hspB) + (size_t)d * 64 * 1536;

        // pipeline prologue: chunks 0,1
#pragma unroll
        for (int pc = 0; pc < 2; pc++) {
            uint32_t dstb = asm_base + (uint32_t)(pc * 64 * ASTR + arow * ASTR + aseg) * 2;
            const __nv_bfloat16* src = hin + arow * 1536 + pc * ACH + aseg;
            CP16(dstb, src); CP16(dstb + 16, src + 8);
            CP16(dstb + 32, src + 16); CP16(dstb + 48, src + 24);
            CP_COMMIT();
        }

        float acc[2][4] = {};
        for (int kc = 0; kc < NCHUNK; kc++) {
            CP_WAIT(1);
            __syncthreads();   // data ready + everyone done with buf being overwritten next
            if (kc + 2 < NCHUNK) {
                int pb = (kc + 2) % 3;
                uint32_t dstb = asm_base + (uint32_t)(pb * 64 * ASTR + arow * ASTR + aseg) * 2;
                const __nv_bfloat16* src = hin + arow * 1536 + (kc + 2) * ACH + aseg;
                CP16(dstb, src); CP16(dstb + 16, src + 8);
                CP16(dstb + 32, src + 16); CP16(dstb + 48, src + 24);
            }
            CP_COMMIT();
            const uint32_t abuf = (uint32_t)((kc % 3) * 64 * ASTR) * 2;
#pragma unroll
            for (int ks = 0; ks < ACH; ks += 16) {
                uint32_t a[4], b[4];
                LDSM_X4(a[0], a[1], a[2], a[3], aAddr0 + abuf + (uint32_t)ks * 2);
                LDSM_X4(b[0], b[1], b[2], b[3], bAddr0 + (uint32_t)(kc * ACH + ks) * 2);
                mma16816(acc[0], a, &b[0]);
                mma16816(acc[1], a, &b[2]);
            }
        }

        // exchange: mma acc -> gates smem
        __syncthreads();
#pragma unroll
        for (int nt = 0; nt < 2; nt++) {
            int c = wn * 16 + nt * 8 + qc;
            gsm[(wm * 16 + qr) * 36 + c]         = acc[nt][0];
            gsm[(wm * 16 + qr) * 36 + c + 1]     = acc[nt][1];
            gsm[(wm * 16 + qr + 8) * 36 + c]     = acc[nt][2];
            gsm[(wm * 16 + qr + 8) * 36 + c + 1] = acc[nt][3];
        }
        __syncthreads();

        // consumer: gate activations + c/h update, 2 outputs per thread
#pragma unroll
        for (int bb = 0; bb < 2; bb++) {
            int b = 2 * tb + bb;
            const float* g = G + (size_t)(t_eff * B_SZ + b) * GCOLS + d * 4 * HIDN;
            int n = n0 + tn;
            float gi = gsm[b * 36 + tn]      + g[n];
            float gf = gsm[b * 36 + 8 + tn]  + g[HIDN + n];
            float gg = gsm[b * 36 + 16 + tn] + g[2 * HIDN + n];
            float go = gsm[b * 36 + 24 + tn] + g[3 * HIDN + n];
            float iv = 1.f / (1.f + expf(-gi));
            float fv = 1.f / (1.f + expf(-gf));
            float gv = tanhf(gg);
            float ov = 1.f / (1.f + expf(-go));
            float cprev = bb ? cv1 : cv0;
            float cval = fv * cprev + iv * gv;
            if (bb) cv1 = cval; else cv0 = cval;
            float hv = ov * tanhf(cval);
            __nv_bfloat16 hi = __float2bfloat16(hv);
            __nv_bfloat16 lo = __float2bfloat16(hv - __bfloat162float(hi));
            __nv_bfloat16* hd = hout + (size_t)b * 1536;
            hd[n] = hi; hd[512 + n] = lo; hd[1024 + n] = hi;
            if (y) y[(size_t)(t_eff * B_SZ + b) * (2 * HIDN) + d * HIDN + n] = hv;
            if (t == T_SEQ - 1) hfin[(size_t)d * B_SZ * HIDN + b * HIDN + n] = hv;
        }

        if (t + 1 < T_SEQ) grid_bar(128);
    }
}

// ---------------- feat = [h_f | h_b | demographic] ----------------
__global__ void build_feat(const float* __restrict__ hfin,
                           const float* __restrict__ demo,
                           float* __restrict__ feat) {
    int i = blockIdx.x * blockDim.x + threadIdx.x;
    if (i >= B_SZ * (2 * HIDN + DEMO)) return;
    int b = i / (2 * HIDN + DEMO), c = i % (2 * HIDN + DEMO);
    float v;
    if (c < HIDN)            v = hfin[b * HIDN + c];
    else if (c < 2 * HIDN)   v = hfin[B_SZ * HIDN + b * HIDN + (c - HIDN)];
    else                     v = demo[b * DEMO + (c - 2 * HIDN)];
    feat[i] = v;
}

// ---------------- launch ----------------
extern "C" void kernel_launch(void* const* d_in, const int* in_sizes, int n_in,
                              void* d_out, int out_size) {
    const int*   codes = (const int*)  d_in[0];
    const float* demo  = (const float*)d_in[1];
    const float* Wc    = (const float*)d_in[2];
    const float* bc    = (const float*)d_in[3];
    const float* w_ih0 = (const float*)d_in[4];
    const float* w_hh0 = (const float*)d_in[5];
    const float* bl0   = (const float*)d_in[6];
    const float* w_ih1 = (const float*)d_in[7];
    const float* w_hh1 = (const float*)d_in[8];
    const float* bl1   = (const float*)d_in[9];
    const float* W1    = (const float*)d_in[10];
    const float* b1    = (const float*)d_in[11];
    const float* W2    = (const float*)d_in[12];
    const float* b2    = (const float*)d_in[13];
    float* out = (float*)d_out;

    float *wcT, *G, *y, *hA, *feat, *hid;
    __nv_bfloat16 *Asp, *Wsp, *Whhsp, *hspA, *hspB;
    cudaGetSymbolAddress((void**)&wcT,   d_WcT);
    cudaGetSymbolAddress((void**)&G,     d_G);
    cudaGetSymbolAddress((void**)&y,     d_y);
    cudaGetSymbolAddress((void**)&hA,    d_hA);
    cudaGetSymbolAddress((void**)&feat,  d_feat);
    cudaGetSymbolAddress((void**)&hid,   d_hid);
    cudaGetSymbolAddress((void**)&Asp,   d_Asp);
    cudaGetSymbolAddress((void**)&Wsp,   d_Wsp);
    cudaGetSymbolAddress((void**)&Whhsp, d_Whhsp);
    cudaGetSymbolAddress((void**)&hspA,  d_hspA);
    cudaGetSymbolAddress((void**)&hspB,  d_hspB);

    const int GEMM_SMEM = STAGES * STG_ELEM * 2 * 2;                     // 61440 B
    cudaFuncSetAttribute(gemm_mma, cudaFuncAttributeMaxDynamicSharedMemorySize, GEMM_SMEM);
    const int SCAN_SMEM = 32 * WSTR * 2 + 3 * 64 * ASTR * 2 + 64 * 36 * 4;  // 160256 B
    cudaFuncSetAttribute(lstm_scan_mma, cudaFuncAttributeMaxDynamicSharedMemorySize, SCAN_SMEM);

    // 1) split W (input proj layer0)  2) Wc^T  3) embed+split  4) gemm L0 [profiled]
    split_W_k<<<(GCOLS * HIDN + 255) / 256, 256>>>(w_ih0, Wsp, GCOLS, HIDN);
    transpose_wc<<<dim3(NCODES / 32, HIDN / 32), dim3(32, 8)>>>(Wc, wcT);
    embed_split<<<ROWS, 256>>>(codes, wcT, bc, Asp);
    gemm_mma<<<dim3(GCOLS / 128, ROWS / 128), 256, GEMM_SMEM>>>(Asp, Wsp, bl0, G, 3 * HIDN);

    // 5-7) layer0 scan
    split_whh<<<(2 * 2048 * 512 + 255) / 256, 256>>>(w_hh0, Whhsp);
    zero_hsp<<<(2 * B_SZ * 1536 + 255) / 256, 256>>>(hspA);
    lstm_scan_mma<<<dim3(B_SZ, 2), 256, SCAN_SMEM>>>(G, Whhsp, hspA, hspB, hA, y);

    // 8-10) layer1 projection
    split_W_k<<<(GCOLS * 2 * HIDN + 255) / 256, 256>>>(w_ih1, Wsp, GCOLS, 2 * HIDN);
    split_A_k<<<(ROWS * 2 * HIDN + 255) / 256, 256>>>(y, Asp, ROWS, 2 * HIDN);
    gemm_mma<<<dim3(GCOLS / 128, ROWS / 128), 256, GEMM_SMEM>>>(Asp, Wsp, bl1, G, 6 * HIDN);

    // 11-13) layer1 scan
    split_whh<<<(2 * 2048 * 512 + 255) / 256, 256>>>(w_hh1, Whhsp);
    zero_hsp<<<(2 * B_SZ * 1536 + 255) / 256, 256>>>(hspA);
    lstm_scan_mma<<<dim3(B_SZ, 2), 256, SCAN_SMEM>>>(G, Whhsp, hspA, hspB, hA, nullptr);

    // 14-16) classifier
    build_feat<<<(B_SZ * (2 * HIDN + DEMO) + 255) / 256, 256>>>(hA, demo, feat);
    sgemm_bias<true ><<<dim3(HIDN / 128, 1), 256>>>(feat, W1, b1, hid, B_SZ, HIDN, 2 * HIDN + DEMO);
    sgemm_bias<false><<<dim3(NCODES / 128, 1), 256>>>(hid, W2, b2, out, B_SZ, NCODES, HIDN);

    (void)in_sizes; (void)n_in; (void)out_size;
}

// round 11
// speedup vs baseline: 1.0025x; 1.0025x over previous
#include <cuda_runtime.h>
#include <cuda_bf16.h>
#include <cstdint>

// Problem constants
#define T_SEQ  50
#define B_SZ   64
#define HIDN   512
#define NCODES 8192
#define KCODES 32
#define DEMO   32
#define ROWS   (T_SEQ * B_SZ)        // 3200
#define GCOLS  (4 * HIDN * 2)        // 4096

// ---------------- scratch (no allocations allowed) ----------------
__device__ float d_WcT [NCODES * HIDN];
__device__ float d_G   [ROWS * GCOLS];
__device__ float d_y   [ROWS * 2 * HIDN];
__device__ float d_hA  [2 * B_SZ * HIDN];                  // final h per dir
__device__ float d_feat[B_SZ * (2 * HIDN + DEMO)];
__device__ float d_hid [B_SZ * HIDN];
__device__ __nv_bfloat16 d_Asp[ROWS * 3 * 1024];           // split A, max K'=3072
__device__ __nv_bfloat16 d_Wsp[GCOLS * 3 * 1024];          // split W (input proj)
__device__ __nv_bfloat16 d_Whhsp[2 * 64 * 32 * 1536];      // split w_hh, block-contiguous
__device__ __nv_bfloat16 d_hspA[2 * B_SZ * 1536];          // h split ping
__device__ __nv_bfloat16 d_hspB[2 * B_SZ * 1536];          // h split pong
// grid-barrier state (monotonic generation; safe across graph replays)
__device__ unsigned g_cnt = 0;
__device__ unsigned g_gen = 0;

// =================== common PTX helpers ===================
__device__ __forceinline__ void mma16816(float* c, const uint32_t* a, const uint32_t* b) {
    asm volatile(
        "mma.sync.aligned.m16n8k16.row.col.f32.bf16.bf16.f32 "
        "{%0,%1,%2,%3}, {%4,%5,%6,%7}, {%8,%9}, {%0,%1,%2,%3};"
        : "+f"(c[0]), "+f"(c[1]), "+f"(c[2]), "+f"(c[3])
        : "r"(a[0]), "r"(a[1]), "r"(a[2]), "r"(a[3]), "r"(b[0]), "r"(b[1]));
}
#define LDSM_X4(r0, r1, r2, r3, addr) \
    asm volatile("ldmatrix.sync.aligned.m8n8.x4.shared.b16 {%0,%1,%2,%3}, [%4];" \
                 : "=r"(r0), "=r"(r1), "=r"(r2), "=r"(r3) : "r"(addr))
#define CP16(dst, src) \
    asm volatile("cp.async.cg.shared.global [%0], [%1], 16;" :: "r"(dst), "l"(src))
#define CP_COMMIT() asm volatile("cp.async.commit_group;" ::: "memory")
#define CP_WAIT(n)  asm volatile("cp.async.wait_group %0;" :: "n"(n) : "memory")

// ---------------- Wc transpose ----------------
__global__ void transpose_wc(const float* __restrict__ Wc, float* __restrict__ WcT) {
    __shared__ float tile[32][33];
    int c0 = blockIdx.x * 32, h0 = blockIdx.y * 32;
    int tx = threadIdx.x, ty = threadIdx.y;
#pragma unroll
    for (int i = 0; i < 32; i += 8)
        tile[ty + i][tx] = Wc[(h0 + ty + i) * NCODES + c0 + tx];
    __syncthreads();
#pragma unroll
    for (int i = 0; i < 32; i += 8)
        WcT[(c0 + ty + i) * HIDN + h0 + tx] = tile[tx][ty + i];
}

// ---------------- multi-hot embed with dedup, fused bf16 split output ----------------
// writes A' rows directly: [hi | lo | hi] at stride 1536 (layer0 K'=1536)
__global__ void embed_split(const int* __restrict__ codes,
                            const float* __restrict__ WcT,
                            const float* __restrict__ bc,
                            __nv_bfloat16* __restrict__ Ap) {
    int blk = blockIdx.x;
    int t = blk >> 6, b = blk & 63;
    __shared__ int sc[KCODES];
    __shared__ int nk;
    int tid = threadIdx.x;
    if (tid < KCODES) sc[tid] = codes[(b * T_SEQ + t) * KCODES + tid];
    __syncthreads();
    if (tid == 0) {
        int cnt = 0;
        for (int j = 0; j < KCODES; j++) {
            int cj = sc[j];
            bool dup = false;
            for (int i = 0; i < cnt; i++)
                if (sc[i] == cj) { dup = true; break; }
            if (!dup) sc[cnt++] = cj;
        }
        nk = cnt;
    }
    __syncthreads();
    int m = nk;
    for (int h = tid; h < HIDN; h += 256) {
        float acc = bc[h];
        for (int j = 0; j < m; j++)
            acc += WcT[sc[j] * HIDN + h];
        __nv_bfloat16 hi = __float2bfloat16(acc);
        __nv_bfloat16 lo = __float2bfloat16(acc - __bfloat162float(hi));
        size_t base = (size_t)blk * 1536;
        Ap[base + h] = hi; Ap[base + 512 + h] = lo; Ap[base + 1024 + h] = hi;
    }
}

// ---------------- bf16 split kernels ----------------
__global__ void split_A_k(const float* __restrict__ A, __nv_bfloat16* __restrict__ Ap,
                          int M, int K) {
    int idx = blockIdx.x * blockDim.x + threadIdx.x;
    if (idx >= M * K) return;
    int m = idx / K, k = idx - m * K;
    float a = A[idx];
    __nv_bfloat16 hi = __float2bfloat16(a);
    __nv_bfloat16 lo = __float2bfloat16(a - __bfloat162float(hi));
    size_t b = (size_t)m * 3 * K;
    Ap[b + k] = hi; Ap[b + K + k] = lo; Ap[b + 2 * K + k] = hi;
}
__global__ void split_W_k(const float* __restrict__ W, __nv_bfloat16* __restrict__ Wp,
                          int N, int K) {
    int idx = blockIdx.x * blockDim.x + threadIdx.x;
    if (idx >= N * K) return;
    int n = idx / K, k = idx - n * K;
    float w = W[idx];
    __nv_bfloat16 hi = __float2bfloat16(w);
    __nv_bfloat16 lo = __float2bfloat16(w - __bfloat162float(hi));
    size_t b = (size_t)n * 3 * K;
    Wp[b + k] = hi; Wp[b + K + k] = hi; Wp[b + 2 * K + k] = lo;
}
// split w_hh [2,2048,512] into block-contiguous layout:
// dst[((d*64+bx)*32 + c)*1536 + {k, 512+k, 1024+k}] = {hi, hi, lo}
// where row r = g*512+n, bx = n>>3, c = g*8 + (n&7)
__global__ void split_whh(const float* __restrict__ whh, __nv_bfloat16* __restrict__ Wp) {
    int idx = blockIdx.x * blockDim.x + threadIdx.x;
    if (idx >= 2 * 2048 * 512) return;
    int k = idx & 511;
    int r = (idx >> 9) & 2047;
    int d = idx >> 20;
    float w = whh[idx];
    __nv_bfloat16 hi = __float2bfloat16(w);
    __nv_bfloat16 lo = __float2bfloat16(w - __bfloat162float(hi));
    int n = r & 511, g = r >> 9;
    int bx = n >> 3, c = g * 8 + (n & 7);
    size_t base = ((size_t)(d * 64 + bx) * 32 + c) * 1536;
    Wp[base + k] = hi; Wp[base + 512 + k] = hi; Wp[base + 1024 + k] = lo;
}

// ---------------- mma.sync bf16 GEMM (input projections) ----------------
#define SSTRIDE 40
#define STAGES  3
#define STG_ELEM (128 * SSTRIDE)
__global__ void __launch_bounds__(256)
gemm_mma(const __nv_bfloat16* __restrict__ Ag,
         const __nv_bfloat16* __restrict__ Wg,
         const float* __restrict__ bias,
         float* __restrict__ C, int K3) {
    extern __shared__ __nv_bfloat16 gsm_[];
    __nv_bfloat16* sA = gsm_;
    __nv_bfloat16* sW = gsm_ + STAGES * STG_ELEM;
    const int tid = threadIdx.x, lane = tid & 31, wid = tid >> 5;
    const int wm = wid & 3, wn = wid >> 2;
    const int m0 = blockIdx.y * 128, n0 = blockIdx.x * 128;
    const int qr = lane >> 2, qc = (lane & 3) * 2;
    float acc[2][8][4] = {};

    const int lrow = tid >> 1;
    const int lseg = (tid & 1) * 16;
    const __nv_bfloat16* Asrc = Ag + (size_t)(m0 + lrow) * K3 + lseg;
    const __nv_bfloat16* Wsrc = Wg + (size_t)(n0 + lrow) * K3 + lseg;
    const uint32_t sA_u32 = (uint32_t)__cvta_generic_to_shared(sA);
    const uint32_t sW_u32 = (uint32_t)__cvta_generic_to_shared(sW);
    const uint32_t dstoff = (uint32_t)(lrow * SSTRIDE + lseg) * 2;

    const uint32_t aAddr0 = sA_u32 +
        (uint32_t)((wm * 32 + (lane & 15)) * SSTRIDE + ((lane >> 4) << 3)) * 2;
    const uint32_t bAddr0 = sW_u32 +
        (uint32_t)((wn * 64 + ((lane >> 4) << 3) + (lane & 7)) * SSTRIDE + (((lane >> 3) & 1) << 3)) * 2;

    const int nkb = K3 / 32;
#pragma unroll
    for (int s = 0; s < STAGES - 1; s++) {
        uint32_t d0 = (uint32_t)(s * STG_ELEM) * 2 + dstoff;
        const __nv_bfloat16* a = Asrc + s * 32;
        const __nv_bfloat16* w = Wsrc + s * 32;
        CP16(sA_u32 + d0, a); CP16(sA_u32 + d0 + 16, a + 8);
        CP16(sW_u32 + d0, w); CP16(sW_u32 + d0 + 16, w + 8);
        CP_COMMIT();
    }

    for (int kb = 0; kb < nkb; kb++) {
        const int lk = kb + STAGES - 1;
        if (lk < nkb) {
            uint32_t d0 = (uint32_t)((lk % STAGES) * STG_ELEM) * 2 + dstoff;
            const __nv_bfloat16* a = Asrc + lk * 32;
            const __nv_bfloat16* w = Wsrc + lk * 32;
            CP16(sA_u32 + d0, a); CP16(sA_u32 + d0 + 16, a + 8);
            CP16(sW_u32 + d0, w); CP16(sW_u32 + d0 + 16, w + 8);
        }
        CP_COMMIT();
        CP_WAIT(STAGES - 1);
        __syncthreads();

        const uint32_t soff = (uint32_t)((kb % STAGES) * STG_ELEM) * 2;
#pragma unroll
        for (int ks = 0; ks < 32; ks += 16) {
            uint32_t af[2][4];
#pragma unroll
            for (int mt = 0; mt < 2; mt++) {
                uint32_t addr = aAddr0 + soff + (uint32_t)(mt * 16 * SSTRIDE + ks) * 2;
                LDSM_X4(af[mt][0], af[mt][1], af[mt][2], af[mt][3], addr);
            }
            uint32_t bfr[4][4];
#pragma unroll
            for (int nt2 = 0; nt2 < 4; nt2++) {
                uint32_t addr = bAddr0 + soff + (uint32_t)(nt2 * 16 * SSTRIDE + ks) * 2;
                LDSM_X4(bfr[nt2][0], bfr[nt2][1], bfr[nt2][2], bfr[nt2][3], addr);
            }
#pragma unroll
            for (int mt = 0; mt < 2; mt++)
#pragma unroll
                for (int nt = 0; nt < 8; nt++)
                    mma16816(acc[mt][nt], af[mt], &bfr[nt >> 1][(nt & 1) * 2]);
        }
        __syncthreads();
    }

#pragma unroll
    for (int mt = 0; mt < 2; mt++) {
        int r = m0 + wm * 32 + mt * 16 + qr;
#pragma unroll
        for (int nt = 0; nt < 8; nt++) {
            int c = n0 + wn * 64 + nt * 8 + qc;
            float b0 = bias[c], b1 = bias[c + 1];
            float2 v0 = make_float2(acc[mt][nt][0] + b0, acc[mt][nt][1] + b1);
            float2 v1 = make_float2(acc[mt][nt][2] + b0, acc[mt][nt][3] + b1);
            *(float2*)(C + (size_t)r * GCOLS + c) = v0;
            *(float2*)(C + (size_t)(r + 8) * GCOLS + c) = v1;
        }
    }
}

// ---------------- fp32 SGEMM (classifier only) ----------------
template <bool RELU>
__global__ void sgemm_bias(const float* __restrict__ A, const float* __restrict__ W,
                           const float* __restrict__ bias, float* __restrict__ C,
                           int M, int N, int K) {
    __shared__ float As[2][8][132];
    __shared__ float Bs[2][8][132];
    const int t  = threadIdx.x;
    const int tx = t & 15, ty = t >> 4;
    const int m0 = blockIdx.y * 128, n0 = blockIdx.x * 128;
    const int lr = t >> 1;
    const int lk = (t & 1) * 4;
    float acc[8][8] = {};
    const bool aval = (m0 + lr) < M;
    const float* Arow = A + (size_t)(m0 + lr) * K + lk;
    const float* Wrow = W + (size_t)(n0 + lr) * K + lk;
    {
        float4 av = aval ? *(const float4*)(Arow) : make_float4(0.f, 0.f, 0.f, 0.f);
        float4 bv = *(const float4*)(Wrow);
        As[0][lk + 0][lr] = av.x; As[0][lk + 1][lr] = av.y; As[0][lk + 2][lr] = av.z; As[0][lk + 3][lr] = av.w;
        Bs[0][lk + 0][lr] = bv.x; Bs[0][lk + 1][lr] = bv.y; Bs[0][lk + 2][lr] = bv.z; Bs[0][lk + 3][lr] = bv.w;
    }
    __syncthreads();
    int buf = 0;
    for (int kb = 8; kb < K; kb += 8) {
        float4 av = aval ? *(const float4*)(Arow + kb) : make_float4(0.f, 0.f, 0.f, 0.f);
        float4 bv = *(const float4*)(Wrow + kb);
#pragma unroll
        for (int k = 0; k < 8; k++) {
            float a[8], b[8];
            *(float4*)&a[0] = *(const float4*)&As[buf][k][ty * 8];
            *(float4*)&a[4] = *(const float4*)&As[buf][k][ty * 8 + 4];
            *(float4*)&b[0] = *(const float4*)&Bs[buf][k][tx * 8];
            *(float4*)&b[4] = *(const float4*)&Bs[buf][k][tx * 8 + 4];
#pragma unroll
            for (int i = 0; i < 8; i++)
#pragma unroll
                for (int j = 0; j < 8; j++)
                    acc[i][j] += a[i] * b[j];
        }
        int nb = buf ^ 1;
        As[nb][lk + 0][lr] = av.x; As[nb][lk + 1][lr] = av.y; As[nb][lk + 2][lr] = av.z; As[nb][lk + 3][lr] = av.w;
        Bs[nb][lk + 0][lr] = bv.x; Bs[nb][lk + 1][lr] = bv.y; Bs[nb][lk + 2][lr] = bv.z; Bs[nb][lk + 3][lr] = bv.w;
        __syncthreads();
        buf = nb;
    }
#pragma unroll
    for (int k = 0; k < 8; k++) {
        float a[8], b[8];
        *(float4*)&a[0] = *(const float4*)&As[buf][k][ty * 8];
        *(float4*)&a[4] = *(const float4*)&As[buf][k][ty * 8 + 4];
        *(float4*)&b[0] = *(const float4*)&Bs[buf][k][tx * 8];
        *(float4*)&b[4] = *(const float4*)&Bs[buf][k][tx * 8 + 4];
#pragma unroll
        for (int i = 0; i < 8; i++)
#pragma unroll
            for (int j = 0; j < 8; j++)
                acc[i][j] += a[i] * b[j];
    }
#pragma unroll
    for (int i = 0; i < 8; i++) {
        int row = m0 + ty * 8 + i;
        if (row >= M) continue;
#pragma unroll
        for (int j = 0; j < 8; j++) {
            int col = n0 + tx * 8 + j;
            float v = acc[i][j] + bias[col];
            if (RELU) v = fmaxf(v, 0.f);
            C[(size_t)row * N + col] = v;
        }
    }
}

// ---------------- zero hsplit ping ----------------
__global__ void zero_hsp(__nv_bfloat16* __restrict__ h) {
    int i = blockIdx.x * blockDim.x + threadIdx.x;
    if (i < 2 * B_SZ * 1536) h[i] = __float2bfloat16(0.f);
}

// ---------------- persistent tensor-core LSTM scan ----------------
// grid (64, 2) = 128 blocks, 1/SM (158KB smem) -> co-resident, spin barrier safe.
// Block: dir d, hidden cols [bx*8, bx*8+8) x 4 gates = 32 output cols, M=64 batch.
// K'=1536 (split-2). W slice persistent in smem; h-split tile via 3-buf cp.async.
#define ACH    128                 // A chunk (k' elems)
#define ASTR   136                 // A smem row stride
#define WSTR   1544                // W smem row stride
#define NCHUNK (1536 / ACH)        // 12
__device__ __forceinline__ void grid_bar(unsigned nb) {
    __syncthreads();
    if (threadIdx.x == 0) {
        __threadfence();
        unsigned target = *(volatile unsigned*)&g_gen + 1;
        if (atomicAdd(&g_cnt, 1u) == nb - 1u) {
            g_cnt = 0;
            __threadfence();
            *(volatile unsigned*)&g_gen = target;
        } else {
            while (*(volatile unsigned*)&g_gen < target) { }
        }
        __threadfence();
    }
    __syncthreads();
}

__global__ void __launch_bounds__(256)
lstm_scan_mma(const float* __restrict__ G,            // [T*64, 4096]
              const __nv_bfloat16* __restrict__ Whhsp, // [2*64 blocks][32][1536]
              __nv_bfloat16* __restrict__ hspA,        // ping (zeroed for t=0)
              __nv_bfloat16* __restrict__ hspB,        // pong
              float* __restrict__ hfin,                // [2,64,512] final h
              float* __restrict__ y) {                 // [T*64, 1024] or nullptr
    extern __shared__ char smx[];
    __nv_bfloat16* Wsm = (__nv_bfloat16*)smx;                          // [32][WSTR]
    __nv_bfloat16* Asm = (__nv_bfloat16*)(smx + 32 * WSTR * 2);        // [3][64][ASTR]
    float* gsm = (float*)(smx + 32 * WSTR * 2 + 3 * 64 * ASTR * 2);    // [64][36]

    const int tid = threadIdx.x, lane = tid & 31, wid = tid >> 5;
    const int wm = wid & 3, wn = wid >> 2;
    const int d = blockIdx.y, bx = blockIdx.x, n0 = bx * 8;
    const int qr = lane >> 2, qc = (lane & 3) * 2;
    const int tn = tid & 7, tb = tid >> 3;

    // load W slice [32][1536] (contiguous in Whhsp) into smem
    {
        const __nv_bfloat16* Wg = Whhsp + (size_t)(d * 64 + bx) * 32 * 1536;
        for (int i = tid; i < 32 * 192; i += 256) {   // 192 = 1536/8 uint4 per row
            int r = i / 192, c8 = (i % 192) * 8;
            *(uint4*)(Wsm + r * WSTR + c8) = *(const uint4*)(Wg + r * 1536 + c8);
        }
    }
    __syncthreads();

    const uint32_t asm_base = (uint32_t)__cvta_generic_to_shared(Asm);
    const uint32_t wsm_base = (uint32_t)__cvta_generic_to_shared(Wsm);
    const int arow = tid >> 2, aseg = (tid & 3) * 32;     // cp.async: 4x16B per thread
    const uint32_t aAddr0 = asm_base +
        (uint32_t)((wm * 16 + (lane & 15)) * ASTR + ((lane >> 4) << 3)) * 2;
    const uint32_t bAddr0 = wsm_base +
        (uint32_t)((wn * 16 + ((lane >> 4) << 3) + (lane & 7)) * WSTR + (((lane >> 3) & 1) << 3)) * 2;

    float cv0 = 0.f, cv1 = 0.f;

    for (int t = 0; t < T_SEQ; t++) {
        const int t_eff = (d == 0) ? t : (T_SEQ - 1 - t);
        const __nv_bfloat16* hin = ((t & 1) ? hspB : hspA) + (size_t)d * 64 * 1536;
        __nv_bfloat16* hout = ((t & 1) ? hspA : hspB) + (size_t)d * 64 * 1536;

        // pipeline prologue: chunks 0,1
#pragma unroll
        for (int pc = 0; pc < 2; pc++) {
            uint32_t dstb = asm_base + (uint32_t)(pc * 64 * ASTR + arow * ASTR + aseg) * 2;
            const __nv_bfloat16* src = hin + arow * 1536 + pc * ACH + aseg;
            CP16(dstb, src); CP16(dstb + 16, src + 8);
            CP16(dstb + 32, src + 16); CP16(dstb + 48, src + 24);
            CP_COMMIT();
        }

        float acc[2][4] = {};
        for (int kc = 0; kc < NCHUNK; kc++) {
            CP_WAIT(1);
            __syncthreads();   // data ready + everyone done with buf being overwritten next
            if (kc + 2 < NCHUNK) {
                int pb = (kc + 2) % 3;
                uint32_t dstb = asm_base + (uint32_t)(pb * 64 * ASTR + arow * ASTR + aseg) * 2;
                const __nv_bfloat16* src = hin + arow * 1536 + (kc + 2) * ACH + aseg;
                CP16(dstb, src); CP16(dstb + 16, src + 8);
                CP16(dstb + 32, src + 16); CP16(dstb + 48, src + 24);
            }
            CP_COMMIT();
            const uint32_t abuf = (uint32_t)((kc % 3) * 64 * ASTR) * 2;
#pragma unroll
            for (int ks = 0; ks < ACH; ks += 16) {
                uint32_t a[4], b[4];
                LDSM_X4(a[0], a[1], a[2], a[3], aAddr0 + abuf + (uint32_t)ks * 2);
                LDSM_X4(b[0], b[1], b[2], b[3], bAddr0 + (uint32_t)(kc * ACH + ks) * 2);
                mma16816(acc[0], a, &b[0]);
                mma16816(acc[1], a, &b[2]);
            }
        }

        // exchange: mma acc -> gates smem
        __syncthreads();
#pragma unroll
        for (int nt = 0; nt < 2; nt++) {
            int c = wn * 16 + nt * 8 + qc;
            gsm[(wm * 16 + qr) * 36 + c]         = acc[nt][0];
            gsm[(wm * 16 + qr) * 36 + c + 1]     = acc[nt][1];
            gsm[(wm * 16 + qr + 8) * 36 + c]     = acc[nt][2];
            gsm[(wm * 16 + qr + 8) * 36 + c + 1] = acc[nt][3];
        }
        __syncthreads();

        // consumer: gate activations + c/h update, 2 outputs per thread
#pragma unroll
        for (int bb = 0; bb < 2; bb++) {
            int b = 2 * tb + bb;
            const float* g = G + (size_t)(t_eff * B_SZ + b) * GCOLS + d * 4 * HIDN;
            int n = n0 + tn;
            float gi = gsm[b * 36 + tn]      + g[n];
            float gf = gsm[b * 36 + 8 + tn]  + g[HIDN + n];
            float gg = gsm[b * 36 + 16 + tn] + g[2 * HIDN + n];
            float go = gsm[b * 36 + 24 + tn] + g[3 * HIDN + n];
            float iv = 1.f / (1.f + expf(-gi));
            float fv = 1.f / (1.f + expf(-gf));
            float gv = tanhf(gg);
            float ov = 1.f / (1.f + expf(-go));
            float cprev = bb ? cv1 : cv0;
            float cval = fv * cprev + iv * gv;
            if (bb) cv1 = cval; else cv0 = cval;
            float hv = ov * tanhf(cval);
            __nv_bfloat16 hi = __float2bfloat16(hv);
            __nv_bfloat16 lo = __float2bfloat16(hv - __bfloat162float(hi));
            __nv_bfloat16* hd = hout + (size_t)b * 1536;
            hd[n] = hi; hd[512 + n] = lo; hd[1024 + n] = hi;
            if (y) y[(size_t)(t_eff * B_SZ + b) * (2 * HIDN) + d * HIDN + n] = hv;
            if (t == T_SEQ - 1) hfin[(size_t)d * B_SZ * HIDN + b * HIDN + n] = hv;
        }

        if (t + 1 < T_SEQ) grid_bar(128);
    }
}

// ---------------- feat = [h_f | h_b | demographic] ----------------
__global__ void build_feat(const float* __restrict__ hfin,
                           const float* __restrict__ demo,
                           float* __restrict__ feat) {
    int i = blockIdx.x * blockDim.x + threadIdx.x;
    if (i >= B_SZ * (2 * HIDN + DEMO)) return;
    int b = i / (2 * HIDN + DEMO), c = i % (2 * HIDN + DEMO);
    float v;
    if (c < HIDN)            v = hfin[b * HIDN + c];
    else if (c < 2 * HIDN)   v = hfin[B_SZ * HIDN + b * HIDN + (c - HIDN)];
    else                     v = demo[b * DEMO + (c - 2 * HIDN)];
    feat[i] = v;
}

// ---------------- launch ----------------
extern "C" void kernel_launch(void* const* d_in, const int* in_sizes, int n_in,
                              void* d_out, int out_size) {
    const int*   codes = (const int*)  d_in[0];
    const float* demo  = (const float*)d_in[1];
    const float* Wc    = (const float*)d_in[2];
    const float* bc    = (const float*)d_in[3];
    const float* w_ih0 = (const float*)d_in[4];
    const float* w_hh0 = (const float*)d_in[5];
    const float* bl0   = (const float*)d_in[6];
    const float* w_ih1 = (const float*)d_in[7];
    const float* w_hh1 = (const float*)d_in[8];
    const float* bl1   = (const float*)d_in[9];
    const float* W1    = (const float*)d_in[10];
    const float* b1    = (const float*)d_in[11];
    const float* W2    = (const float*)d_in[12];
    const float* b2    = (const float*)d_in[13];
    float* out = (float*)d_out;

    float *wcT, *G, *y, *hA, *feat, *hid;
    __nv_bfloat16 *Asp, *Wsp, *Whhsp, *hspA, *hspB;
    cudaGetSymbolAddress((void**)&wcT,   d_WcT);
    cudaGetSymbolAddress((void**)&G,     d_G);
    cudaGetSymbolAddress((void**)&y,     d_y);
    cudaGetSymbolAddress((void**)&hA,    d_hA);
    cudaGetSymbolAddress((void**)&feat,  d_feat);
    cudaGetSymbolAddress((void**)&hid,   d_hid);
    cudaGetSymbolAddress((void**)&Asp,   d_Asp);
    cudaGetSymbolAddress((void**)&Wsp,   d_Wsp);
    cudaGetSymbolAddress((void**)&Whhsp, d_Whhsp);
    cudaGetSymbolAddress((void**)&hspA,  d_hspA);
    cudaGetSymbolAddress((void**)&hspB,  d_hspB);

    const int GEMM_SMEM = STAGES * STG_ELEM * 2 * 2;                     // 61440 B
    cudaFuncSetAttribute(gemm_mma, cudaFuncAttributeMaxDynamicSharedMemorySize, GEMM_SMEM);
    const int SCAN_SMEM = 32 * WSTR * 2 + 3 * 64 * ASTR * 2 + 64 * 36 * 4;  // 160256 B
    cudaFuncSetAttribute(lstm_scan_mma, cudaFuncAttributeMaxDynamicSharedMemorySize, SCAN_SMEM);

    // 1) split W (input proj layer0)  2) Wc^T  3) embed+split  4) gemm L0 [profiled]
    split_W_k<<<(GCOLS * HIDN + 255) / 256, 256>>>(w_ih0, Wsp, GCOLS, HIDN);
    transpose_wc<<<dim3(NCODES / 32, HIDN / 32), dim3(32, 8)>>>(Wc, wcT);
    embed_split<<<ROWS, 256>>>(codes, wcT, bc, Asp);
    gemm_mma<<<dim3(GCOLS / 128, ROWS / 128), 256, GEMM_SMEM>>>(Asp, Wsp, bl0, G, 3 * HIDN);

    // 5-7) layer0 scan
    split_whh<<<(2 * 2048 * 512 + 255) / 256, 256>>>(w_hh0, Whhsp);
    zero_hsp<<<(2 * B_SZ * 1536 + 255) / 256, 256>>>(hspA);
    lstm_scan_mma<<<dim3(B_SZ, 2), 256, SCAN_SMEM>>>(G, Whhsp, hspA, hspB, hA, y);

    // 8-10) layer1 projection
    split_W_k<<<(GCOLS * 2 * HIDN + 255) / 256, 256>>>(w_ih1, Wsp, GCOLS, 2 * HIDN);
    split_A_k<<<(ROWS * 2 * HIDN + 255) / 256, 256>>>(y, Asp, ROWS, 2 * HIDN);
    gemm_mma<<<dim3(GCOLS / 128, ROWS / 128), 256, GEMM_SMEM>>>(Asp, Wsp, bl1, G, 6 * HIDN);

    // 11-13) layer1 scan
    split_whh<<<(2 * 2048 * 512 + 255) / 256, 256>>>(w_hh1, Whhsp);
    zero_hsp<<<(2 * B_SZ * 1536 + 255) / 256, 256>>>(hspA);
    lstm_scan_mma<<<dim3(B_SZ, 2), 256, SCAN_SMEM>>>(G, Whhsp, hspA, hspB, hA, nullptr);

    // 14-16) classifier
    build_feat<<<(B_SZ * (2 * HIDN + DEMO) + 255) / 256, 256>>>(hA, demo, feat);
    sgemm_bias<true ><<<dim3(HIDN / 128, 1), 256>>>(feat, W1, b1, hid, B_SZ, HIDN, 2 * HIDN + DEMO);
    sgemm_bias<false><<<dim3(NCODES / 128, 1), 256>>>(hid, W2, b2, out, B_SZ, NCODES, HIDN);

    (void)in_sizes; (void)n_in; (void)out_size;
}